// round 1
// baseline (speedup 1.0000x reference)
#include <cuda_runtime.h>
#include <cstdint>

// Problem constants (EmbedWeighted: out = inputs @ embeddings)
#define B_DIM 2048
#define V_DIM 2000
#define D_DIM 64
#define NSPLIT 8
#define KSPLIT 256          // splits 0..6 take 256, split 7 takes 2000-7*256 = 208
#define KC 16               // k-chunk staged in smem per iteration

// Split-K partials: 8 * 2048 * 64 floats = 4 MB (static device scratch, allowed)
__device__ float g_partials[NSPLIT][B_DIM][D_DIM];

__device__ __forceinline__ uint32_t f2tf32(float f) {
    uint32_t r;
    asm("cvt.rna.tf32.f32 %0, %1;" : "=r"(r) : "f"(f));
    return r;
}

// Block: 256 threads (8 warps). Tile: M=128, N=64, K=k_len (split).
// Warp layout: warp_m = warp&3 (32 rows each), warp_n = warp>>2 (32 cols each).
// Each warp: 2 m16 tiles x 4 n8 tiles of m16n8k8 tf32 mma.
__global__ __launch_bounds__(256, 1)
void embedweighted_gemm_splitk(const float* __restrict__ inp,
                               const float* __restrict__ emb)
{
    // A: [m][k] stride 20 (bank-conflict-free frag loads: (g*20+t)%32 all distinct)
    // E: [k][n] stride 72 (bank-conflict-free: (t*72+n)%32 = (t*8+n)%32 distinct)
    __shared__ uint32_t As[128 * 20];
    __shared__ uint32_t Es[KC * 72];

    const int ksplit = blockIdx.x;           // 0..7
    const int mtile  = blockIdx.y;           // 0..15
    const int m_base = mtile * 128;
    const int k_base = ksplit * KSPLIT;
    const int k_len  = (ksplit < NSPLIT - 1) ? KSPLIT : (V_DIM - (NSPLIT - 1) * KSPLIT);

    const int tid  = threadIdx.x;
    const int warp = tid >> 5;
    const int lane = tid & 31;
    const int g = lane >> 2;    // groupID (0..7)
    const int t = lane & 3;     // thread-in-group (0..3)

    const int warp_m = warp & 3;    // rows 32*warp_m .. +31
    const int warp_n = warp >> 2;   // cols 32*warp_n .. +31

    float acc[2][4][4];
    #pragma unroll
    for (int i = 0; i < 2; i++)
        #pragma unroll
        for (int j = 0; j < 4; j++)
            #pragma unroll
            for (int r = 0; r < 4; r++)
                acc[i][j][r] = 0.0f;

    for (int kc = 0; kc < k_len; kc += KC) {
        __syncthreads();   // protect smem reuse from previous iteration

        // ---- Stage A chunk: rows [m_base, m_base+128), cols [k_base+kc, +16)
        // 128*16 floats = 512 float4, 2 per thread. Row stride 2000 floats:
        // (anything)*2000*4 bytes is 16B-aligned, k offsets are multiples of 16.
        #pragma unroll
        for (int i = 0; i < 2; i++) {
            int idx = tid + i * 256;            // 0..511
            int r = idx >> 2;                   // row within tile 0..127
            int q = idx & 3;                    // which float4 in the 16-wide row
            const float4 v = *reinterpret_cast<const float4*>(
                inp + (size_t)(m_base + r) * V_DIM + (k_base + kc) + q * 4);
            uint32_t* dst = &As[r * 20 + q * 4];
            dst[0] = f2tf32(v.x); dst[1] = f2tf32(v.y);
            dst[2] = f2tf32(v.z); dst[3] = f2tf32(v.w);
        }

        // ---- Stage E chunk: rows (k) [k_base+kc, +16), cols 0..63
        // 16*64 floats = 256 float4, 1 per thread.
        {
            int r = tid >> 4;                   // 0..15 (k row)
            int q = tid & 15;                   // 0..15 (float4 within 64-wide row)
            const float4 v = *reinterpret_cast<const float4*>(
                emb + (size_t)(k_base + kc + r) * D_DIM + q * 4);
            uint32_t* dst = &Es[r * 72 + q * 4];
            dst[0] = f2tf32(v.x); dst[1] = f2tf32(v.y);
            dst[2] = f2tf32(v.z); dst[3] = f2tf32(v.w);
        }
        __syncthreads();

        // ---- Compute: 2 k-steps of 8
        #pragma unroll
        for (int kk = 0; kk < KC; kk += 8) {
            uint32_t a[2][4];
            uint32_t b[4][2];
            #pragma unroll
            for (int mt = 0; mt < 2; mt++) {
                int m0 = warp_m * 32 + mt * 16;
                a[mt][0] = As[(m0 + g)     * 20 + kk + t];
                a[mt][1] = As[(m0 + g + 8) * 20 + kk + t];
                a[mt][2] = As[(m0 + g)     * 20 + kk + t + 4];
                a[mt][3] = As[(m0 + g + 8) * 20 + kk + t + 4];
            }
            #pragma unroll
            for (int nt = 0; nt < 4; nt++) {
                int n0 = warp_n * 32 + nt * 8;
                b[nt][0] = Es[(kk + t)     * 72 + n0 + g];
                b[nt][1] = Es[(kk + t + 4) * 72 + n0 + g];
            }
            #pragma unroll
            for (int mt = 0; mt < 2; mt++) {
                #pragma unroll
                for (int nt = 0; nt < 4; nt++) {
                    asm volatile(
                        "mma.sync.aligned.m16n8k8.row.col.f32.tf32.tf32.f32 "
                        "{%0,%1,%2,%3}, {%4,%5,%6,%7}, {%8,%9}, {%0,%1,%2,%3};"
                        : "+f"(acc[mt][nt][0]), "+f"(acc[mt][nt][1]),
                          "+f"(acc[mt][nt][2]), "+f"(acc[mt][nt][3])
                        : "r"(a[mt][0]), "r"(a[mt][1]), "r"(a[mt][2]), "r"(a[mt][3]),
                          "r"(b[nt][0]), "r"(b[nt][1]));
                }
            }
        }
    }

    // ---- Epilogue: write this split's 128x64 fp32 partial tile
    float* pp = &g_partials[ksplit][m_base][0];
    #pragma unroll
    for (int mt = 0; mt < 2; mt++) {
        int m0 = warp_m * 32 + mt * 16;
        #pragma unroll
        for (int nt = 0; nt < 4; nt++) {
            int n0 = warp_n * 32 + nt * 8 + 2 * t;
            pp[(m0 + g)     * D_DIM + n0]     = acc[mt][nt][0];
            pp[(m0 + g)     * D_DIM + n0 + 1] = acc[mt][nt][1];
            pp[(m0 + g + 8) * D_DIM + n0]     = acc[mt][nt][2];
            pp[(m0 + g + 8) * D_DIM + n0 + 1] = acc[mt][nt][3];
        }
    }
}

// Deterministic fixed-order reduction of the 8 split-K partials.
__global__ __launch_bounds__(256, 4)
void embedweighted_reduce(float* __restrict__ out)
{
    // total output float4 = 2048*64/4 = 32768; grid 128 * 256 = 32768 threads
    int idx = blockIdx.x * blockDim.x + threadIdx.x;
    const float4* p = reinterpret_cast<const float4*>(&g_partials[0][0][0]);
    float4 s = p[idx];
    #pragma unroll
    for (int sp = 1; sp < NSPLIT; sp++) {
        float4 v = p[sp * (B_DIM * D_DIM / 4) + idx];
        s.x += v.x; s.y += v.y; s.z += v.z; s.w += v.w;
    }
    reinterpret_cast<float4*>(out)[idx] = s;
}

extern "C" void kernel_launch(void* const* d_in, const int* in_sizes, int n_in,
                              void* d_out, int out_size)
{
    const float* inputs     = (const float*)d_in[0];   // (B, V) fp32
    const float* embeddings = (const float*)d_in[1];   // (V, D) fp32
    float* out = (float*)d_out;                        // (B, D) fp32

    dim3 grid(NSPLIT, B_DIM / 128);   // (8, 16) = 128 CTAs
    embedweighted_gemm_splitk<<<grid, 256>>>(inputs, embeddings);

    embedweighted_reduce<<<(B_DIM * D_DIM / 4) / 256, 256>>>(out);
}

// round 2
// speedup vs baseline: 1.1404x; 1.1404x over previous
#include <cuda_runtime.h>
#include <cstdint>

// EmbedWeighted == out(B,D) = inputs(B,V) @ embeddings(V,D)
#define B_DIM 2048
#define V_DIM 2000
#define D_DIM 64
#define NSPLIT 8
#define KSPLIT 256          // splits 0..6: 256, split 7: 208
#define KC 32               // k-chunk per pipeline stage
#define A_STRIDE 36         // floats/row, 4 mod 32 -> conflict-free frag loads
#define E_STRIDE 72         // floats/row, 8 mod 32 -> conflict-free frag loads
#define ABUF (128 * A_STRIDE)
#define EBUF (KC * E_STRIDE)
#define SMEM_BYTES ((2 * ABUF + 2 * EBUF) * 4)

__device__ float g_partials[NSPLIT][B_DIM][D_DIM];   // 4 MB static scratch
__device__ unsigned int g_arrive[B_DIM / 128];       // zero-init, self-resetting
__device__ unsigned int g_done[B_DIM / 128];

__device__ __forceinline__ uint32_t f2tf32(float f) {
    uint32_t r;
    asm("cvt.rna.tf32.f32 %0, %1;" : "=r"(r) : "f"(f));
    return r;
}

__device__ __forceinline__ void cp_async16(float* dst_smem, const float* src, bool pred) {
    uint32_t d = (uint32_t)__cvta_generic_to_shared(dst_smem);
    int sz = pred ? 16 : 0;   // src-size 0 => zero-fill 16B
    asm volatile("cp.async.cg.shared.global [%0], [%1], 16, %2;"
                 :: "r"(d), "l"(src), "r"(sz));
}
__device__ __forceinline__ void cp_commit() {
    asm volatile("cp.async.commit_group;");
}
template <int N>
__device__ __forceinline__ void cp_wait() {
    asm volatile("cp.async.wait_group %0;" :: "n"(N));
}

// Issue one KC-wide stage: A 128x32 fp32, E 32x64 fp32 (raw, converted later).
__device__ __forceinline__ void stage_load(const float* __restrict__ inpS,   // inp + m_base*V + k_base
                                           const float* __restrict__ embS,   // emb + k_base*D
                                           float* __restrict__ As, float* __restrict__ Es,
                                           int kc, int k_len, int tid)
{
    // A: 1024 16B chunks, 4 per thread
    #pragma unroll
    for (int i = 0; i < 4; i++) {
        int idx = tid + i * 256;
        int r = idx >> 3, q = idx & 7;
        int k = kc + q * 4;
        bool p = (k < k_len);                    // k_len multiple of 16 -> whole-chunk validity
        cp_async16(As + r * A_STRIDE + q * 4,
                   inpS + (size_t)r * V_DIM + (p ? k : 0), p);
    }
    // E: 512 16B chunks, 2 per thread
    #pragma unroll
    for (int i = 0; i < 2; i++) {
        int idx = tid + i * 256;
        int r = idx >> 4, q = idx & 15;
        int k = kc + r;
        bool p = (k < k_len);
        cp_async16(Es + r * E_STRIDE + q * 4,
                   embS + (size_t)(p ? k : 0) * D_DIM + q * 4, p);
    }
    cp_commit();
}

// 256 threads, 8 warps. CTA tile M=128, N=64. grid (NSPLIT, 16), one wave.
__global__ __launch_bounds__(256, 1)
void embedweighted_fused(const float* __restrict__ inp,
                         const float* __restrict__ emb,
                         float* __restrict__ out)
{
    extern __shared__ float smem[];
    float* As = smem;                 // 2 buffers
    float* Es = smem + 2 * ABUF;      // 2 buffers

    const int ksplit = blockIdx.x;
    const int mtile  = blockIdx.y;
    const int m_base = mtile * 128;
    const int k_base = ksplit * KSPLIT;
    const int k_len  = (ksplit < NSPLIT - 1) ? KSPLIT : (V_DIM - (NSPLIT - 1) * KSPLIT);
    const int nstages = (k_len + KC - 1) / KC;

    const float* inpS = inp + (size_t)m_base * V_DIM + k_base;
    const float* embS = emb + (size_t)k_base * D_DIM;

    const int tid  = threadIdx.x;
    const int warp = tid >> 5;
    const int lane = tid & 31;
    const int g = lane >> 2;          // 0..7
    const int t = lane & 3;           // 0..3
    const int warp_m = warp & 3;      // 32-row slab
    const int warp_n = warp >> 2;     // 32-col slab

    float acc[2][4][4];
    #pragma unroll
    for (int i = 0; i < 2; i++)
        #pragma unroll
        for (int j = 0; j < 4; j++)
            #pragma unroll
            for (int r = 0; r < 4; r++) acc[i][j][r] = 0.0f;

    // ---- pipelined mainloop ----
    stage_load(inpS, embS, As, Es, 0, k_len, tid);
    int buf = 0;
    for (int it = 0; it < nstages; it++) {
        if (it + 1 < nstages) {
            stage_load(inpS, embS, As + (buf ^ 1) * ABUF, Es + (buf ^ 1) * EBUF,
                       (it + 1) * KC, k_len, tid);
            cp_wait<1>();
        } else {
            cp_wait<0>();
        }
        __syncthreads();

        const float* Ab = As + buf * ABUF;
        const float* Eb = Es + buf * EBUF;
        #pragma unroll
        for (int kk = 0; kk < KC; kk += 8) {
            uint32_t a[2][4], b[4][2];
            #pragma unroll
            for (int mt = 0; mt < 2; mt++) {
                int m0 = warp_m * 32 + mt * 16;
                a[mt][0] = f2tf32(Ab[(m0 + g)     * A_STRIDE + kk + t]);
                a[mt][1] = f2tf32(Ab[(m0 + g + 8) * A_STRIDE + kk + t]);
                a[mt][2] = f2tf32(Ab[(m0 + g)     * A_STRIDE + kk + t + 4]);
                a[mt][3] = f2tf32(Ab[(m0 + g + 8) * A_STRIDE + kk + t + 4]);
            }
            #pragma unroll
            for (int nt = 0; nt < 4; nt++) {
                int n0 = warp_n * 32 + nt * 8;
                b[nt][0] = f2tf32(Eb[(kk + t)     * E_STRIDE + n0 + g]);
                b[nt][1] = f2tf32(Eb[(kk + t + 4) * E_STRIDE + n0 + g]);
            }
            #pragma unroll
            for (int mt = 0; mt < 2; mt++)
                #pragma unroll
                for (int nt = 0; nt < 4; nt++)
                    asm volatile(
                        "mma.sync.aligned.m16n8k8.row.col.f32.tf32.tf32.f32 "
                        "{%0,%1,%2,%3}, {%4,%5,%6,%7}, {%8,%9}, {%0,%1,%2,%3};"
                        : "+f"(acc[mt][nt][0]), "+f"(acc[mt][nt][1]),
                          "+f"(acc[mt][nt][2]), "+f"(acc[mt][nt][3])
                        : "r"(a[mt][0]), "r"(a[mt][1]), "r"(a[mt][2]), "r"(a[mt][3]),
                          "r"(b[nt][0]), "r"(b[nt][1]));
        }
        __syncthreads();   // protect buf reuse at it+2
        buf ^= 1;
    }

    // ---- write 128x64 fp32 partial tile ----
    float* pp = &g_partials[ksplit][m_base][0];
    #pragma unroll
    for (int mt = 0; mt < 2; mt++) {
        int m0 = warp_m * 32 + mt * 16;
        #pragma unroll
        for (int nt = 0; nt < 4; nt++) {
            int n0 = warp_n * 32 + nt * 8 + 2 * t;
            pp[(m0 + g)     * D_DIM + n0]     = acc[mt][nt][0];
            pp[(m0 + g)     * D_DIM + n0 + 1] = acc[mt][nt][1];
            pp[(m0 + g + 8) * D_DIM + n0]     = acc[mt][nt][2];
            pp[(m0 + g + 8) * D_DIM + n0 + 1] = acc[mt][nt][3];
        }
    }

    // ---- fused deterministic split-K reduction ----
    // release-arrive: all CTA stores ordered before the counter bump
    __syncthreads();
    if (tid == 0) {
        __threadfence();
        atomicAdd(&g_arrive[mtile], 1u);
        unsigned v;
        do {
            asm volatile("ld.acquire.gpu.u32 %0, [%1];" : "=r"(v) : "l"(&g_arrive[mtile]));
            if (v >= NSPLIT) break;
            __nanosleep(64);
        } while (true);
    }
    __syncthreads();   // bar cumulativity propagates tid0's acquire to the CTA

    // This CTA reduces rows [m_base + ksplit*16, +16): 256 float4 = 1/thread.
    {
        int r = tid >> 4, q = tid & 15;
        int off = (m_base + ksplit * 16 + r) * (D_DIM / 4) + q;
        const float4* p = reinterpret_cast<const float4*>(&g_partials[0][0][0]);
        float4 s = p[off];
        #pragma unroll
        for (int sp = 1; sp < NSPLIT; sp++) {   // fixed order -> deterministic
            float4 v = p[(size_t)sp * (B_DIM * D_DIM / 4) + off];
            s.x += v.x; s.y += v.y; s.z += v.z; s.w += v.w;
        }
        reinterpret_cast<float4*>(out)[off] = s;
    }

    // second handshake: last CTA of the mtile resets counters for graph replay
    __syncthreads();
    if (tid == 0) {
        unsigned d = atomicAdd(&g_done[mtile], 1u);
        if (d == NSPLIT - 1) {
            atomicExch(&g_arrive[mtile], 0u);
            atomicExch(&g_done[mtile], 0u);
        }
    }
}

extern "C" void kernel_launch(void* const* d_in, const int* in_sizes, int n_in,
                              void* d_out, int out_size)
{
    const float* inputs     = (const float*)d_in[0];   // (B, V) fp32
    const float* embeddings = (const float*)d_in[1];   // (V, D) fp32
    float* out = (float*)d_out;                        // (B, D) fp32

    cudaFuncSetAttribute(embedweighted_fused,
                         cudaFuncAttributeMaxDynamicSharedMemorySize, SMEM_BYTES);

    dim3 grid(NSPLIT, B_DIM / 128);   // 128 CTAs == one wave (<=148 SMs)
    embedweighted_fused<<<grid, 256, SMEM_BYTES>>>(inputs, embeddings, out);
}